// round 4
// baseline (speedup 1.0000x reference)
#include <cuda_runtime.h>
#include <cuda_bf16.h>

#define NPTS   65536
#define CHN    256
#define BATCH  16
#define LOUT   8192
#define LOG2L  13
#define TJ     128

// g_off[b] = first index with batch id >= b; g_off[BATCH] = NPTS.
__device__ int g_off[BATCH + 1];

// ------------------------------------------------------- boundary detect ---
__global__ void boundary_kernel(const int* __restrict__ batch) {
    int i = blockIdx.x * blockDim.x + threadIdx.x;
    if (i >= NPTS) return;
    int cur  = batch[i];
    int prev = (i == 0) ? -1 : batch[i - 1];
    for (int bb = prev + 1; bb <= cur; bb++) g_off[bb] = i;
    if (i == NPTS - 1) {
        for (int bb = cur + 1; bb <= BATCH; bb++) g_off[bb] = NPTS;
    }
}

// ------------------------------------------------------------- points ------
__global__ void points_kernel(const float* __restrict__ px,
                              float* __restrict__ out) {
    int idx = blockIdx.x * blockDim.x + threadIdx.x;  // 0 .. B*L/4-1
    if (idx >= BATCH * LOUT / 4) return;
    int j = (idx & (LOUT / 4 - 1)) * 4;
    int b = idx >> (LOG2L - 2);
    int off = g_off[b];
    int cnt = g_off[b + 1] - off;
    float4 ox, oy, oz;
    #pragma unroll
    for (int t = 0; t < 4; t++) {
        int src = off + (int)(((unsigned)((j + t) * cnt)) >> LOG2L);
        const float* p = px + 3 * src;
        ((float*)&ox)[t] = p[0];
        ((float*)&oy)[t] = p[1];
        ((float*)&oz)[t] = p[2];
    }
    size_t base = (size_t)b * 3 * LOUT + j;
    __stcs((float4*)(out + base),            ox);
    __stcs((float4*)(out + base + LOUT),     oy);
    __stcs((float4*)(out + base + 2 * LOUT), oz);
}

// ------------------------------------------------------------ features -----
// One block per (j-tile of 128, batch b); block loops over all 8 channel
// subtiles of 32. Smem: transposed, XOR-swizzled, pad-free:
//   word(c,row) = c*128 + (row ^ 4*(c>>2))
// Load phase : 4x LDG.128/thread (rows fixed across subtiles, bases precomputed)
//              + 16 STS.32 scatter; banks = q + 4*(w^s) -> all 32, conflict-free.
// Store phase: 4x (LDS.128 + STG.128); LDS phase-groups = (L^w)&7 distinct;
//              XOR preserves low bits so components emerge in row order.
// Register double-buffer: LDGs for subtile k+1 issue during store phase of k.
__global__ __launch_bounds__(256)
void feat_kernel(const float4* __restrict__ feat4, float* __restrict__ out) {
    __shared__ float tileT[32 * 128];      // 16 KB
    __shared__ int   s_src[TJ];

    int bid = blockIdx.x;                  // 0..1023
    int j0  = (bid & 63) << 7;
    int b   = bid >> 6;
    int tid = threadIdx.x;
    int w = tid >> 5, L = tid & 31;
    int q = L >> 3, s = L & 7;             // load-phase lane decomposition

    if (tid < TJ) {
        int off = g_off[b];
        int cnt = g_off[b + 1] - off;
        s_src[tid] = off + (int)(((unsigned)((j0 + tid) * cnt)) >> LOG2L);
    }
    __syncthreads();

    // 4 row base pointers, constant across the 8 subtiles.
    const float4* base[4];
    #pragma unroll
    for (int m = 0; m < 4; m++)
        base[m] = feat4 + (size_t)s_src[32 * m + 4 * w + q] * (CHN / 4);

    // Store-phase output base: channels 4w+kk, j = j0 + 4L.
    float* outb = out + ((size_t)b * CHN + 4 * w) * LOUT + j0 + 4 * L;

    float4 v[4], v2[4];
    #pragma unroll
    for (int m = 0; m < 4; m++) v[m] = __ldg(base[m] + s);   // subtile 0

    #pragma unroll
    for (int k = 0; k < 8; k++) {
        __syncthreads();                   // prev store phase done with tileT
        // STS scatter: row = 32m+4w+q, local channel c = 4s+i  (c>>2 == s)
        #pragma unroll
        for (int m = 0; m < 4; m++) {
            int row = 32 * m + 4 * w + q;
            #pragma unroll
            for (int i = 0; i < 4; i++) {
                int c = 4 * s + i;
                tileT[c * 128 + (row ^ (4 * s))] = ((const float*)&v[m])[i];
            }
        }
        if (k < 7) {                       // prefetch next subtile's loads
            #pragma unroll
            for (int m = 0; m < 4; m++)
                v2[m] = __ldg(base[m] + (k + 1) * 8 + s);
        }
        __syncthreads();                   // tileT ready
        // Store phase: warp w owns local channels 4w..4w+3.
        #pragma unroll
        for (int kk = 0; kk < 4; kk++) {
            int c = 4 * w + kk;            // c>>2 == w
            float4 d = *(const float4*)&tileT[c * 128 + ((4 * L) ^ (4 * w))];
            __stcs((float4*)(outb + (size_t)(k * 32 + kk) * LOUT), d);
        }
        #pragma unroll
        for (int m = 0; m < 4; m++) v[m] = v2[m];
    }
}

// ------------------------------------------------------------- launch ------
extern "C" void kernel_launch(void* const* d_in, const int* in_sizes, int n_in,
                              void* d_out, int out_size) {
    const float* points_x = (const float*)d_in[0];   // [N,3]
    const float* feat     = (const float*)d_in[1];   // [N,C]
    const int*   batch    = (const int*)d_in[2];     // [N]

    float* out_point = (float*)d_out;                              // [B,3,L]
    float* out_feat  = (float*)d_out + (size_t)BATCH * 3 * LOUT;   // [B,C,L]

    boundary_kernel<<<NPTS / 256, 256>>>(batch);

    int npt = BATCH * LOUT / 4;
    points_kernel<<<(npt + 255) / 256, 256>>>(points_x, out_point);

    feat_kernel<<<(LOUT / TJ) * BATCH, 256>>>((const float4*)feat, out_feat);
}

// round 5
// speedup vs baseline: 1.1915x; 1.1915x over previous
#include <cuda_runtime.h>
#include <cuda_bf16.h>

#define NPTS   65536
#define CHN    256
#define BATCH  16
#define LOUT   8192
#define LOG2L  13

// g_off[b] = first index with batch id >= b; g_off[BATCH] = NPTS.
__device__ int g_off[BATCH + 1];

// ------------------------------------------------------- boundary detect ---
// batch is sorted. One thread per element, coalesced, no atomics.
__global__ void boundary_kernel(const int* __restrict__ batch) {
    int i = blockIdx.x * blockDim.x + threadIdx.x;
    if (i >= NPTS) return;
    int cur  = batch[i];
    int prev = (i == 0) ? -1 : batch[i - 1];
    for (int bb = prev + 1; bb <= cur; bb++) g_off[bb] = i;
    if (i == NPTS - 1) {
        for (int bb = cur + 1; bb <= BATCH; bb++) g_off[bb] = NPTS;
    }
}

// ----------------------------------------------------------- main gather ---
// blocks [0, PT_BLOCKS)              : points gather (float4 writes)
// blocks [PT_BLOCKS, PT_BLOCKS+8192) : feature gather-transpose, register-only.
//
// Feature mapping: one thread owns channels [4c4, 4c4+4) x j in [4jq, 4jq+4).
//   idx = fb*256+tid ; jq = idx & 2047 ; c4 = (idx>>11) & 63 ; b = idx>>17
// Loads : 4x LDG.128 feat[src(4jq+t), 4c4..4c4+3]  (independent, MLP=4;
//         ~2 unique rows due to ~2x upsample -> L1 hits on duplicates)
// Writes: 4x STG.128, lanes = consecutive jq -> 512B contiguous per warp.
// 4x4 register transpose in between. No smem tile, no barriers.
#define PT_BLOCKS 128

__global__ __launch_bounds__(256)
void gather_kernel(const float* __restrict__ px,
                   const float4* __restrict__ feat4,
                   float* __restrict__ out_point,
                   float* __restrict__ out_feat) {
    __shared__ int s_off, s_cnt;
    int bid = blockIdx.x;
    int tid = threadIdx.x;

    if (bid < PT_BLOCKS) {
        // ---- points: 32768 threads; thread = 4 consecutive j of one b.
        int idx = bid * 256 + tid;            // 0..32767
        int b = idx >> 11;                    // 2048 threads per b, block-uniform
        if (tid == 0) { s_off = g_off[b]; s_cnt = g_off[b + 1] - g_off[b]; }
        __syncthreads();
        int off = s_off, cnt = s_cnt;
        int j = (idx & 2047) * 4;
        float4 ox, oy, oz;
        #pragma unroll
        for (int t = 0; t < 4; t++) {
            int src = off + (int)(((unsigned)((j + t) * cnt)) >> LOG2L);
            const float* p = px + 3 * src;
            ((float*)&ox)[t] = p[0];
            ((float*)&oy)[t] = p[1];
            ((float*)&oz)[t] = p[2];
        }
        size_t base = (size_t)b * 3 * LOUT + j;
        __stcs((float4*)(out_point + base),            ox);
        __stcs((float4*)(out_point + base + LOUT),     oy);
        __stcs((float4*)(out_point + base + 2 * LOUT), oz);
        return;
    }

    // ---- features ----
    int idx = (bid - PT_BLOCKS) * 256 + tid;  // 0 .. 2097151
    int jq = idx & 2047;
    int c4 = (idx >> 11) & 63;
    int b  = idx >> 17;                       // block-uniform
    if (tid == 0) { s_off = g_off[b]; s_cnt = g_off[b + 1] - g_off[b]; }
    __syncthreads();
    int off = s_off, cnt = s_cnt;
    int j0 = jq * 4;

    float4 v0 = __ldg(feat4 + (size_t)(off + (int)(((unsigned)((j0 + 0) * cnt)) >> LOG2L)) * (CHN / 4) + c4);
    float4 v1 = __ldg(feat4 + (size_t)(off + (int)(((unsigned)((j0 + 1) * cnt)) >> LOG2L)) * (CHN / 4) + c4);
    float4 v2 = __ldg(feat4 + (size_t)(off + (int)(((unsigned)((j0 + 2) * cnt)) >> LOG2L)) * (CHN / 4) + c4);
    float4 v3 = __ldg(feat4 + (size_t)(off + (int)(((unsigned)((j0 + 3) * cnt)) >> LOG2L)) * (CHN / 4) + c4);

    // 4x4 register transpose + coalesced float4 stores (channels 4c4..4c4+3).
    float* ob = out_feat + ((size_t)b * CHN + 4 * c4) * LOUT + j0;
    float4 o;
    o.x = v0.x; o.y = v1.x; o.z = v2.x; o.w = v3.x;
    __stcs((float4*)(ob + 0 * LOUT), o);
    o.x = v0.y; o.y = v1.y; o.z = v2.y; o.w = v3.y;
    __stcs((float4*)(ob + 1 * LOUT), o);
    o.x = v0.z; o.y = v1.z; o.z = v2.z; o.w = v3.z;
    __stcs((float4*)(ob + 2 * LOUT), o);
    o.x = v0.w; o.y = v1.w; o.z = v2.w; o.w = v3.w;
    __stcs((float4*)(ob + 3 * LOUT), o);
}

// ------------------------------------------------------------- launch ------
extern "C" void kernel_launch(void* const* d_in, const int* in_sizes, int n_in,
                              void* d_out, int out_size) {
    const float* points_x = (const float*)d_in[0];   // [N,3]
    const float* feat     = (const float*)d_in[1];   // [N,C]
    const int*   batch    = (const int*)d_in[2];     // [N]

    float* out_point = (float*)d_out;                              // [B,3,L]
    float* out_feat  = (float*)d_out + (size_t)BATCH * 3 * LOUT;   // [B,C,L]

    boundary_kernel<<<NPTS / 256, 256>>>(batch);

    int nblocks = PT_BLOCKS + (BATCH * (CHN / 4) * (LOUT / 4)) / 256;  // 128 + 8192
    gather_kernel<<<nblocks, 256>>>(points_x, (const float4*)feat,
                                    out_point, out_feat);
}